// round 10
// baseline (speedup 1.0000x reference)
#include <cuda_runtime.h>
#include <cuda_fp16.h>
#include <cstdint>

#define B_    8
#define CIN   256
#define COUT  256
#define CINFO 256
#define LL    32768
#define CHUNK 32                 // l-positions per chunk
#define NCH   (LL / CHUNK)       // 1024 chunks per batch
#define JPITCH 40                // words per jj row (32 l + 8 pad)
#define KTSZ  (8 * JPITCH)       // 320 words per kt slab
#define BUFW  (16 * KTSZ)        // 5120 words per x buffer (20 KB)
#define RED_OFF (2 * BUFW)       // reduction area: 2 bufs x 16 warps x 4 rg x 32 lanes x 4 words
#define RED_WORDS (2 * 16 * 4 * 32 * 4)
#define SMEM_WORDS (RED_OFF + RED_WORDS)   // 10240 + 16384 = 26624 words = 104 KB

// ---------------- device scratch ----------------
__device__ float g_Ain [B_ * CIN * 2];     // [b][2i + r]
__device__ float g_Aout[B_ * 2 * COUT];    // [b][r*256 + o]

// ---------------- helpers ----------------
__device__ __forceinline__ uint32_t pack_f16x2(float lo, float hi) {
    uint32_t r;  // second source -> low half
    asm("cvt.rn.f16x2.f32 %0, %1, %2;" : "=r"(r) : "f"(hi), "f"(lo));
    return r;
}

__device__ __forceinline__ void mma16816(float* c, const uint32_t* A, uint32_t b0, uint32_t b1) {
    asm volatile(
        "mma.sync.aligned.m16n8k16.row.col.f32.f16.f16.f32 "
        "{%0,%1,%2,%3}, {%4,%5,%6,%7}, {%8,%9}, {%0,%1,%2,%3};"
        : "+f"(c[0]), "+f"(c[1]), "+f"(c[2]), "+f"(c[3])
        : "r"(A[0]), "r"(A[1]), "r"(A[2]), "r"(A[3]), "r"(b0), "r"(b1));
}

// ---------------- prologue: adapter vectors (1 k per warp) ----------------
__global__ void lora_adapters_kernel(const float* __restrict__ g_out,
                                     const float* __restrict__ W_ain,
                                     const float* __restrict__ W_aout) {
    __shared__ float4 sg4[CINFO / 4];
    int bx = blockIdx.x;
    int b = bx >> 7;
    int kbase = (bx & 127) * 4;
    if (threadIdx.x < CINFO / 4)
        sg4[threadIdx.x] = ((const float4*)(g_out + b * CINFO))[threadIdx.x];
    __syncthreads();
    int w = threadIdx.x >> 5, lane = threadIdx.x & 31;
    int k = kbase + w;
    const float4* wi = (const float4*)(W_ain  + (size_t)k * CINFO);
    const float4* wo = (const float4*)(W_aout + (size_t)k * CINFO);
    float ai = 0.f, ao = 0.f;
#pragma unroll
    for (int h = 0; h < 2; ++h) {
        int i = lane + 32 * h;
        float4 gv = sg4[i];
        float4 a = wi[i], o = wo[i];
        ai += a.x * gv.x + a.y * gv.y + a.z * gv.z + a.w * gv.w;
        ao += o.x * gv.x + o.y * gv.y + o.z * gv.z + o.w * gv.w;
    }
#pragma unroll
    for (int off = 16; off; off >>= 1) {
        ai += __shfl_xor_sync(0xFFFFFFFFu, ai, off);
        ao += __shfl_xor_sync(0xFFFFFFFFu, ao, off);
    }
    if (lane == 0) {
        g_Ain [b * 512 + k] = ai;
        g_Aout[b * 512 + k] = ao;
    }
}

// ---------------- main persistent GEMM: 16 warps, K-split ----------------
// Warp (wm = w&7, kh = w>>3): cout rows [32wm, 32wm+32), kt in [8kh, 8kh+8).
// A frags (fused Weff) = 64 regs, acc = 32 regs -> ~128 regs @ 512 threads.
// Partial-K sums exchanged via double-buffered SMEM reduction:
//   kh0 stores its acc for nt{2,3}, epilogues nt{0,1} (reads partner's);
//   kh1 stores nt{0,1}, epilogues nt{2,3}. One __syncthreads per chunk.
// SMEM x buffer word(kt, jj, l) = kt*320 + jj*40 + l: LDS bank (8q+l) mod 32
// is a full permutation per phase -> conflict-free; STS.128 phases cover all
// banks; reduction float4 [w][rg][lane] layout is trivially conflict-free.
__global__ void __launch_bounds__(512, 1)
lora_main_kernel(const float* __restrict__ x, const float* __restrict__ W_main,
                 const float* __restrict__ b_main, float* __restrict__ out,
                 int per_batch) {
    extern __shared__ uint32_t sm[];
    const int tid = threadIdx.x;
    const int lane = tid & 31;
    const int w = tid >> 5;            // 0..15
    const int wm = w & 7;
    const int kh = w >> 3;             // 0..1
    const int cta = blockIdx.x;
    const int b  = cta / per_batch;
    const int jb = cta % per_batch;
    const int s = (jb * NCH) / per_batch;
    const int e = ((jb + 1) * NCH) / per_batch;
    if (s >= e) return;

    const float* xb = x   + (size_t)b * ((size_t)CIN * LL);
    float*       ob = out + (size_t)b * ((size_t)COUT * LL);

    const int obase = wm * 32;
    const int gg = lane >> 2;    // 0..7
    const int q  = lane & 3;     // 0..3
    const int ktbase = 8 * kh;

    // ---- fused Weff: A fragments for this warp's K-half ----
    uint32_t A0[8][4], A1[8][4];
    {
        const float* Ain = g_Ain  + b * 512;
        const float* Aou = g_Aout + b * 512;
        const int rows[4] = { obase + gg, obase + 8 + gg, obase + 16 + gg, obase + 24 + gg };
        float p0[4], p1[4];
#pragma unroll
        for (int m = 0; m < 4; ++m) {
            p0[m] = Aou[rows[m]];
            p1[m] = Aou[256 + rows[m]];
        }
#pragma unroll
        for (int k8 = 0; k8 < 8; ++k8) {
            int kt = ktbase + k8;
            float4 u = *(const float4*)(Ain + 32 * kt + 4 * q);
            float4 v = *(const float4*)(Ain + 32 * kt + 16 + 4 * q);
#pragma unroll
            for (int m = 0; m < 4; ++m) {
                const float* wr = W_main + (size_t)rows[m] * CIN + 16 * kt;
                float2 wlo = *(const float2*)(wr + 2 * q);
                float2 whi = *(const float2*)(wr + 8 + 2 * q);
                uint32_t flo = pack_f16x2(wlo.x + p0[m] * u.x + p1[m] * u.y,
                                          wlo.y + p0[m] * u.z + p1[m] * u.w);
                uint32_t fhi = pack_f16x2(whi.x + p0[m] * v.x + p1[m] * v.y,
                                          whi.y + p0[m] * v.z + p1[m] * v.w);
                if (m < 2) { A0[k8][m] = flo; A0[k8][2 + m] = fhi; }
                else       { A1[k8][m - 2] = flo; A1[k8][m] = fhi; }
            }
        }
    }
    const float bg00 = b_main[obase + gg];
    const float bg01 = b_main[obase + 8 + gg];
    const float bg10 = b_main[obase + 16 + gg];
    const float bg11 = b_main[obase + 24 + gg];

    // LDG staging: warp w loads x rows [16w, 16w+16) == kt slab w.
    // thread: pair p = (lane>>3) + 4j (j=0,1), float4 at l = (lane&7)*4.
    float4 sa[2], sb[2];
    const int c4 = (lane & 7) * 4;
    const int ph = lane >> 3;

    auto ldg_issue = [&](int chunk) {
        const float* base = xb + (size_t)chunk * CHUNK + c4;
#pragma unroll
        for (int j = 0; j < 2; ++j) {
            int row0 = w * 16 + 2 * (ph + 4 * j);
            sa[j] = *(const float4*)(base + (size_t)row0 * LL);
            sb[j] = *(const float4*)(base + (size_t)(row0 + 1) * LL);
        }
    };

    auto pack_sts = [&](int bufsel) {
        uint32_t* dst = sm + bufsel * BUFW + w * KTSZ;
#pragma unroll
        for (int j = 0; j < 2; ++j) {
            int p = ph + 4 * j;
            uint4 v;
            v.x = pack_f16x2(sa[j].x, sb[j].x);
            v.y = pack_f16x2(sa[j].y, sb[j].y);
            v.z = pack_f16x2(sa[j].z, sb[j].z);
            v.w = pack_f16x2(sa[j].w, sb[j].w);
            *(uint4*)(dst + p * JPITCH + c4) = v;
        }
    };

    ldg_issue(s);
    pack_sts(0);
    __syncthreads();

    const int partner = (kh ? wm : wm + 8);   // the other K-half warp

    for (int c = s; c < e; ++c) {
        const int cb = (c - s) & 1;
        const bool more = (c + 1) < e;
        if (more) ldg_issue(c + 1);

        float acc0[4][4], acc1[4][4];
#pragma unroll
        for (int nt = 0; nt < 4; ++nt)
#pragma unroll
            for (int r = 0; r < 4; ++r) { acc0[nt][r] = 0.f; acc1[nt][r] = 0.f; }

        const uint32_t* buf = sm + cb * BUFW + ktbase * KTSZ;
#pragma unroll
        for (int nt = 0; nt < 4; ++nt) {
            const int l = nt * 8 + gg;
            const uint32_t* p0 = buf + q * JPITCH + l;           // jj = q
            const uint32_t* p1 = buf + (q + 4) * JPITCH + l;     // jj = q+4
#pragma unroll
            for (int k8 = 0; k8 < 8; ++k8) {
                uint32_t b0 = p0[k8 * KTSZ];
                uint32_t b1 = p1[k8 * KTSZ];
                mma16816(acc0[nt], A0[k8], b0, b1);
                mma16816(acc1[nt], A1[k8], b0, b1);
            }
        }

        if (more) pack_sts(cb ^ 1);

        // store own half's partials for the nt range the PARTNER epilogues
        {
            float* red = (float*)(sm + RED_OFF) + ((cb * 16 + w) * 4) * 32 * 4 + lane * 4;
            const int ntoff = kh ? 0 : 2;   // kh0 stores nt{2,3}; kh1 stores nt{0,1}
#pragma unroll
            for (int t = 0; t < 2; ++t) {
                int nt = ntoff + t;
                *(float4*)(red + (t * 2 + 0) * 128) =
                    make_float4(acc0[nt][0], acc0[nt][1], acc0[nt][2], acc0[nt][3]);
                *(float4*)(red + (t * 2 + 1) * 128) =
                    make_float4(acc1[nt][0], acc1[nt][1], acc1[nt][2], acc1[nt][3]);
            }
        }
        __syncthreads();

        // epilogue: this warp outputs nt = kh*2 + {0,1}
        {
            const float* red = (const float*)(sm + RED_OFF) + ((cb * 16 + partner) * 4) * 32 * 4 + lane * 4;
            const size_t lcb = (size_t)c * CHUNK + 2 * q;
#pragma unroll
            for (int t = 0; t < 2; ++t) {
                int nt = kh * 2 + t;
                float4 v0 = *(const float4*)(red + (t * 2 + 0) * 128);
                float4 v1 = *(const float4*)(red + (t * 2 + 1) * 128);
                const size_t lc = lcb + nt * 8;
                float* o00 = ob + (size_t)(obase + gg)      * LL + lc;
                float* o01 = ob + (size_t)(obase + gg + 8)  * LL + lc;
                float* o10 = ob + (size_t)(obase + 16 + gg) * LL + lc;
                float* o11 = ob + (size_t)(obase + 24 + gg) * LL + lc;
                *(float2*)o00 = make_float2(acc0[nt][0] + v0.x + bg00, acc0[nt][1] + v0.y + bg00);
                *(float2*)o01 = make_float2(acc0[nt][2] + v0.z + bg01, acc0[nt][3] + v0.w + bg01);
                *(float2*)o10 = make_float2(acc1[nt][0] + v1.x + bg10, acc1[nt][1] + v1.y + bg10);
                *(float2*)o11 = make_float2(acc1[nt][2] + v1.z + bg11, acc1[nt][3] + v1.w + bg11);
            }
        }
    }
}

// ---------------- launch ----------------
extern "C" void kernel_launch(void* const* d_in, const int* in_sizes, int n_in,
                              void* d_out, int out_size) {
    const float* x      = (const float*)d_in[0];
    const float* g_out  = (const float*)d_in[1];
    const float* W_main = (const float*)d_in[2];
    const float* b_main = (const float*)d_in[3];
    const float* W_ain  = (const float*)d_in[4];
    const float* W_aout = (const float*)d_in[5];
    float* out = (float*)d_out;

    int dev = 0, sms = 148;
    cudaGetDevice(&dev);
    cudaDeviceGetAttribute(&sms, cudaDevAttrMultiProcessorCount, dev);
    int per_batch = sms / B_;
    if (per_batch < 1) per_batch = 1;
    if (per_batch > NCH) per_batch = NCH;

    size_t smem = (size_t)SMEM_WORDS * sizeof(uint32_t);  // 104 KB
    cudaFuncSetAttribute(lora_main_kernel, cudaFuncAttributeMaxDynamicSharedMemorySize, (int)smem);

    lora_adapters_kernel<<<B_ * 128, 128>>>(g_out, W_ain, W_aout);
    lora_main_kernel<<<per_batch * B_, 512, smem>>>(x, W_main, b_main, out, per_batch);
}

// round 11
// speedup vs baseline: 1.4857x; 1.4857x over previous
#include <cuda_runtime.h>
#include <cuda_fp16.h>
#include <cstdint>

#define B_    8
#define CIN   256
#define COUT  256
#define CINFO 256
#define LL    32768
#define CHUNK 64                 // l-positions per chunk
#define NCH   (LL / CHUNK)       // 512 chunks per batch
#define JPITCH 72                // words per jj row (64 l + 8 pad)
#define KTSZ  (8 * JPITCH)       // 576 words per kt slab
#define BUFW  (16 * KTSZ)        // 9216 words per buffer (36 KB)

// ---------------- device scratch ----------------
__device__ float g_Ain [B_ * CIN * 2];     // [b][2i + r]
__device__ float g_Aout[B_ * 2 * COUT];    // [b][r*256 + o]

// ---------------- helpers ----------------
__device__ __forceinline__ uint32_t pack_f16x2(float lo, float hi) {
    uint32_t r;  // second source -> low half
    asm("cvt.rn.f16x2.f32 %0, %1, %2;" : "=r"(r) : "f"(hi), "f"(lo));
    return r;
}

__device__ __forceinline__ void mma16816(float* c, const uint32_t* A, uint32_t b0, uint32_t b1) {
    asm volatile(
        "mma.sync.aligned.m16n8k16.row.col.f32.f16.f16.f32 "
        "{%0,%1,%2,%3}, {%4,%5,%6,%7}, {%8,%9}, {%0,%1,%2,%3};"
        : "+f"(c[0]), "+f"(c[1]), "+f"(c[2]), "+f"(c[3])
        : "r"(A[0]), "r"(A[1]), "r"(A[2]), "r"(A[3]), "r"(b0), "r"(b1));
}

// ---------------- prologue: adapter vectors ----------------
__global__ void lora_adapters_kernel(const float* __restrict__ g_out,
                                     const float* __restrict__ W_ain,
                                     const float* __restrict__ W_aout) {
    __shared__ float4 sg4[CINFO / 4];
    int bx = blockIdx.x;
    int b = bx >> 7;
    int kbase = (bx & 127) * 4;
    if (threadIdx.x < CINFO / 4)
        sg4[threadIdx.x] = ((const float4*)(g_out + b * CINFO))[threadIdx.x];
    __syncthreads();
    int w = threadIdx.x >> 5, lane = threadIdx.x & 31;
    int k = kbase + w;
    const float4* wi = (const float4*)(W_ain  + (size_t)k * CINFO);
    const float4* wo = (const float4*)(W_aout + (size_t)k * CINFO);
    float ai = 0.f, ao = 0.f;
#pragma unroll
    for (int h = 0; h < 2; ++h) {
        int i = lane + 32 * h;
        float4 gv = sg4[i];
        float4 a = wi[i], o = wo[i];
        ai += a.x * gv.x + a.y * gv.y + a.z * gv.z + a.w * gv.w;
        ao += o.x * gv.x + o.y * gv.y + o.z * gv.z + o.w * gv.w;
    }
#pragma unroll
    for (int off = 16; off; off >>= 1) {
        ai += __shfl_xor_sync(0xFFFFFFFFu, ai, off);
        ao += __shfl_xor_sync(0xFFFFFFFFu, ao, off);
    }
    if (lane == 0) {
        g_Ain [b * 512 + k] = ai;
        g_Aout[b * 512 + k] = ao;
    }
}

// ---------------- main persistent GEMM (R7 structure, CHUNK=64) ----------------
// 256 threads / 8 warps. Warp w owns cout rows [32w, 32w+32), full N=64
// (8 n-tiles), K=256 (16 kt) -> 256 MMAs/warp/chunk. A (fused Weff) frags
// register-resident (128 regs). Next-chunk x load split into 2 stages
// (16 rows each), each hidden under one MMA half-block of 128 MMAs.
//
// SMEM word(kt, jj, l) = kt*576 + jj*72 + l. Consumer bank
// (72q + 8nt + gg) mod 32 = (8q+8nt+gg) mod 32: full 32-bank permutation
// for b0 (jj=q) and b1 (jj=q+4, +288 = 0 mod 32). STS.128 phases of 8
// lanes cover banks 4*l4..+3 over l4 range -> all 32 banks. Conflict-free.
__global__ void __launch_bounds__(256, 1)
lora_main_kernel(const float* __restrict__ x, const float* __restrict__ W_main,
                 const float* __restrict__ b_main, float* __restrict__ out,
                 int per_batch) {
    extern __shared__ uint32_t sm[];   // 2 * BUFW words = 72 KB
    const int tid = threadIdx.x;
    const int lane = tid & 31;
    const int w = tid >> 5;            // 0..7
    const int cta = blockIdx.x;
    const int b  = cta / per_batch;
    const int jb = cta % per_batch;
    const int s = (jb * NCH) / per_batch;
    const int e = ((jb + 1) * NCH) / per_batch;
    if (s >= e) return;

    const float* xb = x   + (size_t)b * ((size_t)CIN * LL);
    float*       ob = out + (size_t)b * ((size_t)COUT * LL);

    const int obase = w * 32;
    const int gg = lane >> 2;    // 0..7 (MMA row group)
    const int q  = lane & 3;     // 0..3

    // ---- fused Weff: A fragments built from W_main + adapters ----
    uint32_t A0[16][4], A1[16][4];
    {
        const float* Ain = g_Ain  + b * 512;
        const float* Aou = g_Aout + b * 512;
        const int rows[4] = { obase + gg, obase + 8 + gg, obase + 16 + gg, obase + 24 + gg };
        float p0[4], p1[4];
#pragma unroll
        for (int m = 0; m < 4; ++m) {
            p0[m] = Aou[rows[m]];
            p1[m] = Aou[256 + rows[m]];
        }
#pragma unroll
        for (int kt = 0; kt < 16; ++kt) {
            float4 u = *(const float4*)(Ain + 32 * kt + 4 * q);
            float4 v = *(const float4*)(Ain + 32 * kt + 16 + 4 * q);
#pragma unroll
            for (int m = 0; m < 4; ++m) {
                const float* wr = W_main + (size_t)rows[m] * CIN + 16 * kt;
                float2 wlo = *(const float2*)(wr + 2 * q);
                float2 whi = *(const float2*)(wr + 8 + 2 * q);
                uint32_t flo = pack_f16x2(wlo.x + p0[m] * u.x + p1[m] * u.y,
                                          wlo.y + p0[m] * u.z + p1[m] * u.w);
                uint32_t fhi = pack_f16x2(whi.x + p0[m] * v.x + p1[m] * v.y,
                                          whi.y + p0[m] * v.z + p1[m] * v.w);
                if (m < 2) { A0[kt][m] = flo; A0[kt][2 + m] = fhi; }
                else       { A1[kt][m - 2] = flo; A1[kt][m] = fhi; }
            }
        }
    }
    const float bg00 = b_main[obase + gg];
    const float bg01 = b_main[obase + 8 + gg];
    const float bg10 = b_main[obase + 16 + gg];
    const float bg11 = b_main[obase + 24 + gg];

    // LDG staging for one 16-row stage: l4 = lane&15 (float4 pos), rp = lane>>4.
    // Stage h covers rows [32w + 16h, 32w + 16h + 16): pairs p = rp + 2j, j=0..3.
    float4 sa[4], sb[4];
    const int l4x4 = (lane & 15) * 4;
    const int rp = lane >> 4;

    auto ldg_stage = [&](int chunk, int h) {
        const float* base = xb + (size_t)chunk * CHUNK + l4x4;
#pragma unroll
        for (int j = 0; j < 4; ++j) {
            int row0 = w * 32 + 16 * h + 2 * (rp + 2 * j);
            sa[j] = *(const float4*)(base + (size_t)row0 * LL);
            sb[j] = *(const float4*)(base + (size_t)(row0 + 1) * LL);
        }
    };

    auto pack_sts = [&](int bufsel, int h) {
        uint32_t* dst = sm + bufsel * BUFW + (2 * w + h) * KTSZ;
#pragma unroll
        for (int j = 0; j < 4; ++j) {
            int jj = rp + 2 * j;
            uint4 v;
            v.x = pack_f16x2(sa[j].x, sb[j].x);
            v.y = pack_f16x2(sa[j].y, sb[j].y);
            v.z = pack_f16x2(sa[j].z, sb[j].z);
            v.w = pack_f16x2(sa[j].w, sb[j].w);
            *(uint4*)(dst + jj * JPITCH + l4x4) = v;
        }
    };

    ldg_stage(s, 0); pack_sts(0, 0);
    ldg_stage(s, 1); pack_sts(0, 1);
    __syncthreads();

    for (int c = s; c < e; ++c) {
        const int cb = (c - s) & 1;
        const bool more = (c + 1) < e;
        if (more) ldg_stage(c + 1, 0);

        float acc0[8][4], acc1[8][4];
#pragma unroll
        for (int nt = 0; nt < 8; ++nt)
#pragma unroll
            for (int r = 0; r < 4; ++r) { acc0[nt][r] = 0.f; acc1[nt][r] = 0.f; }

        const uint32_t* buf = sm + cb * BUFW;

        // MMA half 0: nt 0..3 (hides stage-0 LDG latency)
#pragma unroll
        for (int nt = 0; nt < 4; ++nt) {
            const int l = nt * 8 + gg;
            const uint32_t* p0 = buf + q * JPITCH + l;
            const uint32_t* p1 = buf + (q + 4) * JPITCH + l;
#pragma unroll
            for (int kt = 0; kt < 16; ++kt) {
                uint32_t b0 = p0[kt * KTSZ];
                uint32_t b1 = p1[kt * KTSZ];
                mma16816(acc0[nt], A0[kt], b0, b1);
                mma16816(acc1[nt], A1[kt], b0, b1);
            }
        }

        if (more) { pack_sts(cb ^ 1, 0); ldg_stage(c + 1, 1); }

        // MMA half 1: nt 4..7 (hides stage-1 LDG latency)
#pragma unroll
        for (int nt = 4; nt < 8; ++nt) {
            const int l = nt * 8 + gg;
            const uint32_t* p0 = buf + q * JPITCH + l;
            const uint32_t* p1 = buf + (q + 4) * JPITCH + l;
#pragma unroll
            for (int kt = 0; kt < 16; ++kt) {
                uint32_t b0 = p0[kt * KTSZ];
                uint32_t b1 = p1[kt * KTSZ];
                mma16816(acc0[nt], A0[kt], b0, b1);
                mma16816(acc1[nt], A1[kt], b0, b1);
            }
        }

        if (more) pack_sts(cb ^ 1, 1);

        // epilogue: bias + coalesced float2 stores (8 nt x 4 row-groups)
        {
            const size_t lc = (size_t)c * CHUNK + 2 * q;
            float* o00 = ob + (size_t)(obase + gg)      * LL + lc;
            float* o01 = ob + (size_t)(obase + gg + 8)  * LL + lc;
            float* o10 = ob + (size_t)(obase + 16 + gg) * LL + lc;
            float* o11 = ob + (size_t)(obase + 24 + gg) * LL + lc;
#pragma unroll
            for (int nt = 0; nt < 8; ++nt) {
                *(float2*)(o00 + nt * 8) = make_float2(acc0[nt][0] + bg00, acc0[nt][1] + bg00);
                *(float2*)(o01 + nt * 8) = make_float2(acc0[nt][2] + bg01, acc0[nt][3] + bg01);
                *(float2*)(o10 + nt * 8) = make_float2(acc1[nt][0] + bg10, acc1[nt][1] + bg10);
                *(float2*)(o11 + nt * 8) = make_float2(acc1[nt][2] + bg11, acc1[nt][3] + bg11);
            }
        }
        __syncthreads();
    }
}

// ---------------- launch ----------------
extern "C" void kernel_launch(void* const* d_in, const int* in_sizes, int n_in,
                              void* d_out, int out_size) {
    const float* x      = (const float*)d_in[0];
    const float* g_out  = (const float*)d_in[1];
    const float* W_main = (const float*)d_in[2];
    const float* b_main = (const float*)d_in[3];
    const float* W_ain  = (const float*)d_in[4];
    const float* W_aout = (const float*)d_in[5];
    float* out = (float*)d_out;

    int dev = 0, sms = 148;
    cudaGetDevice(&dev);
    cudaDeviceGetAttribute(&sms, cudaDevAttrMultiProcessorCount, dev);
    int per_batch = sms / B_;
    if (per_batch < 1) per_batch = 1;
    if (per_batch > NCH) per_batch = NCH;

    size_t smem = 2ull * BUFW * sizeof(uint32_t);  // 72 KB
    cudaFuncSetAttribute(lora_main_kernel, cudaFuncAttributeMaxDynamicSharedMemorySize, (int)smem);

    lora_adapters_kernel<<<B_ * 128, 128>>>(g_out, W_ain, W_aout);
    lora_main_kernel<<<per_batch * B_, 256, smem>>>(x, W_main, b_main, out, per_batch);
}

// round 12
// speedup vs baseline: 1.5099x; 1.0163x over previous
#include <cuda_runtime.h>
#include <cuda_fp16.h>
#include <cstdint>

#define B_    8
#define CIN   256
#define COUT  256
#define CINFO 256
#define LL    32768
#define CHUNK 32                 // l-positions per chunk
#define NCH   (LL / CHUNK)       // 1024 chunks per batch
#define JPITCH 40                // words per jj row (32 l + 8 pad)
#define KTSZ  (8 * JPITCH)       // 320 words per kt slab
#define BUFW  (16 * KTSZ)        // 5120 words per buffer (20 KB)
#define NBUF  4                  // 4-deep ring, barrier every 2 chunks

// ---------------- device scratch ----------------
__device__ float  g_Ain [B_ * CIN * 2];     // [b][2i + r]
__device__ float  g_Aout[B_ * 2 * COUT];    // [b][r*256 + o]
__device__ __half g_Weff[B_ * COUT * CIN];  // [b][o][i]

// ---------------- helpers ----------------
__device__ __forceinline__ uint32_t pack_f16x2(float lo, float hi) {
    uint32_t r;  // second source -> low half
    asm("cvt.rn.f16x2.f32 %0, %1, %2;" : "=r"(r) : "f"(hi), "f"(lo));
    return r;
}

__device__ __forceinline__ void mma16816(float* c, const uint32_t* A, uint32_t b0, uint32_t b1) {
    asm volatile(
        "mma.sync.aligned.m16n8k16.row.col.f32.f16.f16.f32 "
        "{%0,%1,%2,%3}, {%4,%5,%6,%7}, {%8,%9}, {%0,%1,%2,%3};"
        : "+f"(c[0]), "+f"(c[1]), "+f"(c[2]), "+f"(c[3])
        : "r"(A[0]), "r"(A[1]), "r"(A[2]), "r"(A[3]), "r"(b0), "r"(b1));
}

// ---------------- prologue 1: adapter vectors ----------------
__global__ void lora_adapters_kernel(const float* __restrict__ g_out,
                                     const float* __restrict__ W_ain,
                                     const float* __restrict__ W_aout) {
    __shared__ float4 sg4[CINFO / 4];
    int bx = blockIdx.x;
    int b = bx >> 7;
    int kbase = (bx & 127) * 4;
    if (threadIdx.x < CINFO / 4)
        sg4[threadIdx.x] = ((const float4*)(g_out + b * CINFO))[threadIdx.x];
    __syncthreads();
    int w = threadIdx.x >> 5, lane = threadIdx.x & 31;
    int k = kbase + w;
    const float4* wi = (const float4*)(W_ain  + (size_t)k * CINFO);
    const float4* wo = (const float4*)(W_aout + (size_t)k * CINFO);
    float ai = 0.f, ao = 0.f;
#pragma unroll
    for (int h = 0; h < 2; ++h) {
        int i = lane + 32 * h;
        float4 gv = sg4[i];
        float4 a = wi[i], o = wo[i];
        ai += a.x * gv.x + a.y * gv.y + a.z * gv.z + a.w * gv.w;
        ao += o.x * gv.x + o.y * gv.y + o.z * gv.z + o.w * gv.w;
    }
#pragma unroll
    for (int off = 16; off; off >>= 1) {
        ai += __shfl_xor_sync(0xFFFFFFFFu, ai, off);
        ao += __shfl_xor_sync(0xFFFFFFFFu, ao, off);
    }
    if (lane == 0) {
        g_Ain [b * 512 + k] = ai;
        g_Aout[b * 512 + k] = ao;
    }
}

// ---------------- prologue 2: effective weight (fp16) ----------------
__global__ void lora_weff_kernel(const float* __restrict__ W_main) {
    int o = blockIdx.x, b = blockIdx.y, i = threadIdx.x;
    float wm = W_main[o * CIN + i];
    float a0 = g_Ain [b * 512 + i * 2 + 0];
    float a1 = g_Ain [b * 512 + i * 2 + 1];
    float q0 = g_Aout[b * 512 + o];
    float q1 = g_Aout[b * 512 + COUT + o];
    g_Weff[(size_t)b * (COUT * CIN) + o * CIN + i] = __float2half(wm + q0 * a0 + q1 * a1);
}

// ---------------- main persistent GEMM (R7 engine + 4-buffer ring) ----------------
// 256 threads / 8 warps. Warp w owns cout rows [32w, 32w+32) (2 m-tiles),
// full N=32 (4 n-tiles), K=256 (16 kt) -> 128 MMAs/warp/chunk. A (Weff)
// fragments register-resident. 4-deep SMEM ring, __syncthreads every 2
// chunks (write of buf (rel+2)&3 vs its last read at rel-2 always has a
// barrier between, both parities; bufs 0/1 first read after prologue sync).
//
// SMEM word(kt, jj, l) = kt*320 + jj*40 + l. Consumer bank (8q+l) mod 32 is
// a full permutation per phase for b0 (jj=q) and b1 (jj=q+4); STS.128
// phases cover all 32 banks. Conflict-free (unchanged from R7).
__global__ void __launch_bounds__(256, 1)
lora_main_kernel(const float* __restrict__ x, const float* __restrict__ b_main,
                 float* __restrict__ out, int per_batch) {
    extern __shared__ uint32_t sm[];   // NBUF * BUFW words = 80 KB
    const int tid = threadIdx.x;
    const int lane = tid & 31;
    const int w = tid >> 5;            // 0..7
    const int cta = blockIdx.x;
    const int b  = cta / per_batch;
    const int jb = cta % per_batch;
    const int s = (jb * NCH) / per_batch;
    const int e = ((jb + 1) * NCH) / per_batch;
    if (s >= e) return;

    const float* xb = x   + (size_t)b * ((size_t)CIN * LL);
    float*       ob = out + (size_t)b * ((size_t)COUT * LL);

    const int obase = w * 32;
    const int gg = lane >> 2;    // 0..7 (MMA row group)
    const int q  = lane & 3;     // 0..3

    // ---- A fragments (Weff) resident in registers ----
    uint32_t A0[16][4], A1[16][4];
    {
        const __half* Wb = g_Weff + (size_t)b * (COUT * CIN);
        const uint32_t* r00 = (const uint32_t*)(Wb + (size_t)(obase + gg)      * CIN);
        const uint32_t* r01 = (const uint32_t*)(Wb + (size_t)(obase + gg + 8)  * CIN);
        const uint32_t* r10 = (const uint32_t*)(Wb + (size_t)(obase + 16 + gg) * CIN);
        const uint32_t* r11 = (const uint32_t*)(Wb + (size_t)(obase + 24 + gg) * CIN);
#pragma unroll
        for (int kt = 0; kt < 16; ++kt) {
            A0[kt][0] = r00[kt * 8 + q];
            A0[kt][1] = r01[kt * 8 + q];
            A0[kt][2] = r00[kt * 8 + 4 + q];
            A0[kt][3] = r01[kt * 8 + 4 + q];
            A1[kt][0] = r10[kt * 8 + q];
            A1[kt][1] = r11[kt * 8 + q];
            A1[kt][2] = r10[kt * 8 + 4 + q];
            A1[kt][3] = r11[kt * 8 + 4 + q];
        }
    }
    const float bg00 = b_main[obase + gg];
    const float bg01 = b_main[obase + 8 + gg];
    const float bg10 = b_main[obase + 16 + gg];
    const float bg11 = b_main[obase + 24 + gg];

    // LDG staging: thread loads row-pair p = (lane>>3) + 4j, float4 at l = (lane&7)*4
    float4 sa[4], sb[4];
    const int c4 = (lane & 7) * 4;
    const int ph = lane >> 3;

    auto ldg_issue = [&](int chunk) {
        const float* base = xb + (size_t)chunk * CHUNK + c4;
#pragma unroll
        for (int j = 0; j < 4; ++j) {
            int row0 = w * 32 + 2 * (ph + 4 * j);
            sa[j] = *(const float4*)(base + (size_t)row0 * LL);
            sb[j] = *(const float4*)(base + (size_t)(row0 + 1) * LL);
        }
    };

    auto pack_sts = [&](int bufsel) {
        uint32_t* dst = sm + bufsel * BUFW;
#pragma unroll
        for (int j = 0; j < 4; ++j) {
            int p  = ph + 4 * j;
            int kt = 2 * w + (p >> 3);
            int jj = p & 7;
            uint4 v;
            v.x = pack_f16x2(sa[j].x, sb[j].x);
            v.y = pack_f16x2(sa[j].y, sb[j].y);
            v.z = pack_f16x2(sa[j].z, sb[j].z);
            v.w = pack_f16x2(sa[j].w, sb[j].w);
            *(uint4*)(dst + kt * KTSZ + jj * JPITCH + c4) = v;
        }
    };

    // prologue: fill bufs 0 and 1
    ldg_issue(s);
    pack_sts(0);
    if (s + 1 < e) { ldg_issue(s + 1); pack_sts(1); }
    __syncthreads();

    for (int c = s; c < e; ++c) {
        const int rel = c - s;
        const int bb = rel & 3;
        const bool morel = (c + 2) < e;
        if (morel) ldg_issue(c + 2);   // staged across the MMA block

        float acc0[4][4], acc1[4][4];
#pragma unroll
        for (int nt = 0; nt < 4; ++nt)
#pragma unroll
            for (int r = 0; r < 4; ++r) { acc0[nt][r] = 0.f; acc1[nt][r] = 0.f; }

        const uint32_t* buf = sm + bb * BUFW;
#pragma unroll
        for (int nt = 0; nt < 4; ++nt) {
            const int l = nt * 8 + gg;
            const uint32_t* p0 = buf + q * JPITCH + l;          // jj = q
            const uint32_t* p1 = buf + (q + 4) * JPITCH + l;    // jj = q+4
#pragma unroll
            for (int kt = 0; kt < 16; ++kt) {
                uint32_t b0 = p0[kt * KTSZ];
                uint32_t b1 = p1[kt * KTSZ];
                mma16816(acc0[nt], A0[kt], b0, b1);
                mma16816(acc1[nt], A1[kt], b0, b1);
            }
        }

        if (morel) pack_sts((rel + 2) & 3);   // pack AFTER MMAs: LDG hidden

        // epilogue: bias + coalesced float2 stores
        {
            const size_t lc = (size_t)c * CHUNK + 2 * q;
            float* o00 = ob + (size_t)(obase + gg)      * LL + lc;
            float* o01 = ob + (size_t)(obase + gg + 8)  * LL + lc;
            float* o10 = ob + (size_t)(obase + 16 + gg) * LL + lc;
            float* o11 = ob + (size_t)(obase + 24 + gg) * LL + lc;
#pragma unroll
            for (int nt = 0; nt < 4; ++nt) {
                *(float2*)(o00 + nt * 8) = make_float2(acc0[nt][0] + bg00, acc0[nt][1] + bg00);
                *(float2*)(o01 + nt * 8) = make_float2(acc0[nt][2] + bg01, acc0[nt][3] + bg01);
                *(float2*)(o10 + nt * 8) = make_float2(acc1[nt][0] + bg10, acc1[nt][1] + bg10);
                *(float2*)(o11 + nt * 8) = make_float2(acc1[nt][2] + bg11, acc1[nt][3] + bg11);
            }
        }

        if (rel & 1) __syncthreads();   // barrier every 2 chunks
    }
}

// ---------------- launch ----------------
extern "C" void kernel_launch(void* const* d_in, const int* in_sizes, int n_in,
                              void* d_out, int out_size) {
    const float* x      = (const float*)d_in[0];
    const float* g_out  = (const float*)d_in[1];
    const float* W_main = (const float*)d_in[2];
    const float* b_main = (const float*)d_in[3];
    const float* W_ain  = (const float*)d_in[4];
    const float* W_aout = (const float*)d_in[5];
    float* out = (float*)d_out;

    int dev = 0, sms = 148;
    cudaGetDevice(&dev);
    cudaDeviceGetAttribute(&sms, cudaDevAttrMultiProcessorCount, dev);
    int per_batch = sms / B_;
    if (per_batch < 1) per_batch = 1;
    if (per_batch > NCH) per_batch = NCH;

    size_t smem = (size_t)NBUF * BUFW * sizeof(uint32_t);  // 80 KB
    cudaFuncSetAttribute(lora_main_kernel, cudaFuncAttributeMaxDynamicSharedMemorySize, (int)smem);

    lora_adapters_kernel<<<B_ * 128, 128>>>(g_out, W_ain, W_aout);
    lora_weff_kernel<<<dim3(COUT, B_), CIN>>>(W_main);
    lora_main_kernel<<<per_batch * B_, 256, smem>>>(x, b_main, out, per_batch);
}